// round 1
// baseline (speedup 1.0000x reference)
#include <cuda_runtime.h>

#define BB 4
#define CC_DIM 512
#define TT_DIM 4096

// Scratch (device globals; no allocation allowed in kernel_launch)
__device__ float g_q[(size_t)BB * TT_DIM * CC_DIM];
__device__ float g_k[(size_t)BB * TT_DIM * CC_DIM];
__device__ float g_v[(size_t)BB * TT_DIM * CC_DIM];
__device__ float g_h[(size_t)BB * TT_DIM * CC_DIM];
__device__ float g_s[(size_t)BB * TT_DIM * TT_DIM];   // 256 MB attention matrix

// ---------------------------------------------------------------------------
// Kernel 1: QKV projections.  q[b,t,o] = sum_c W[o,c] * x[b,c,t] + bias[o]
// out layout: [B][T][C] (t-major rows, channel contiguous)
// ---------------------------------------------------------------------------
__global__ __launch_bounds__(256) void k_proj(
    const float* __restrict__ x,
    const float* __restrict__ Wq, const float* __restrict__ bq,
    const float* __restrict__ Wk, const float* __restrict__ bk,
    const float* __restrict__ Wv, const float* __restrict__ bv)
{
    const int t0 = blockIdx.x * 64;
    const int o0 = blockIdx.y * 64;
    const int m  = blockIdx.z % 3;
    const int b  = blockIdx.z / 3;

    const float* W    = (m == 0) ? Wq : (m == 1) ? Wk : Wv;
    const float* bias = (m == 0) ? bq : (m == 1) ? bk : bv;
    float*       out  = (m == 0) ? g_q : (m == 1) ? g_k : g_v;

    __shared__ float xs[16][64];   // xs[c][t]
    __shared__ float ws[16][65];   // ws[c][o]

    const int tid = threadIdx.x;
    const int row = tid >> 4;      // -> t micro index
    const int col = tid & 15;      // -> o micro index

    float acc[4][4] = {};

    for (int c0 = 0; c0 < CC_DIM; c0 += 16) {
        #pragma unroll
        for (int l = 0; l < 4; l++) {
            int idx = tid + l * 256;
            int cc = idx >> 6, tt = idx & 63;
            xs[cc][tt] = x[((size_t)b * CC_DIM + c0 + cc) * TT_DIM + t0 + tt];
        }
        #pragma unroll
        for (int l = 0; l < 4; l++) {
            int idx = tid + l * 256;
            int oo = idx >> 4, cc = idx & 15;
            ws[cc][oo] = W[(size_t)(o0 + oo) * CC_DIM + c0 + cc];
        }
        __syncthreads();
        #pragma unroll
        for (int cc = 0; cc < 16; cc++) {
            float xv[4], wv[4];
            #pragma unroll
            for (int i = 0; i < 4; i++) xv[i] = xs[cc][row + i * 16];
            #pragma unroll
            for (int j = 0; j < 4; j++) wv[j] = ws[cc][col + j * 16];
            #pragma unroll
            for (int i = 0; i < 4; i++)
                #pragma unroll
                for (int j = 0; j < 4; j++)
                    acc[i][j] += xv[i] * wv[j];
        }
        __syncthreads();
    }

    #pragma unroll
    for (int i = 0; i < 4; i++) {
        int t = t0 + row + i * 16;
        #pragma unroll
        for (int j = 0; j < 4; j++) {
            int o = o0 + col + j * 16;
            out[((size_t)b * TT_DIM + t) * CC_DIM + o] = acc[i][j] + bias[o];
        }
    }
}

// ---------------------------------------------------------------------------
// Kernel 2: S[b,t,s] = scale * q[b,t,:] . k[b,s,:]  for tile(s) <= tile(t)
// ---------------------------------------------------------------------------
__global__ __launch_bounds__(256) void k_scores()
{
    const int qt = blockIdx.x;
    const int st = blockIdx.y;
    const int b  = blockIdx.z;
    if (st > qt) return;           // causal tile skip (uniform per block)

    const int t0 = qt * 64;
    const int s0 = st * 64;

    __shared__ float qs[16][65];   // qs[c][t]
    __shared__ float ks[16][65];   // ks[c][s]

    const int tid = threadIdx.x;
    const int row = tid >> 4;      // -> t
    const int col = tid & 15;      // -> s

    float acc[4][4] = {};

    for (int c0 = 0; c0 < CC_DIM; c0 += 16) {
        #pragma unroll
        for (int l = 0; l < 4; l++) {
            int idx = tid + l * 256;
            int tt = idx >> 4, cc = idx & 15;
            qs[cc][tt] = g_q[((size_t)b * TT_DIM + t0 + tt) * CC_DIM + c0 + cc];
        }
        #pragma unroll
        for (int l = 0; l < 4; l++) {
            int idx = tid + l * 256;
            int ss = idx >> 4, cc = idx & 15;
            ks[cc][ss] = g_k[((size_t)b * TT_DIM + s0 + ss) * CC_DIM + c0 + cc];
        }
        __syncthreads();
        #pragma unroll
        for (int cc = 0; cc < 16; cc++) {
            float qv[4], kv[4];
            #pragma unroll
            for (int i = 0; i < 4; i++) qv[i] = qs[cc][row + i * 16];
            #pragma unroll
            for (int j = 0; j < 4; j++) kv[j] = ks[cc][col + j * 16];
            #pragma unroll
            for (int i = 0; i < 4; i++)
                #pragma unroll
                for (int j = 0; j < 4; j++)
                    acc[i][j] += qv[i] * kv[j];
        }
        __syncthreads();
    }

    const float scale = 0.04419417382415922f;  // 1/sqrt(512)
    #pragma unroll
    for (int i = 0; i < 4; i++) {
        int t = t0 + row + i * 16;
        #pragma unroll
        for (int j = 0; j < 4; j++) {
            int s = s0 + col + j * 16;
            g_s[(size_t)b * TT_DIM * TT_DIM + (size_t)t * TT_DIM + s] = acc[i][j] * scale;
        }
    }
}

// ---------------------------------------------------------------------------
// Kernel 3: row softmax over s in [0, t], and zero-fill (t, tile_end) so the
// PV GEMM can read whole 64-wide tiles.
// ---------------------------------------------------------------------------
__global__ __launch_bounds__(256) void k_softmax()
{
    const int b = blockIdx.x / TT_DIM;
    const int t = blockIdx.x % TT_DIM;
    float* p = g_s + (size_t)b * TT_DIM * TT_DIM + (size_t)t * TT_DIM;
    const int n    = t + 1;
    const int ncap = ((t >> 6) + 1) << 6;

    const int tid  = threadIdx.x;
    const int lane = tid & 31;
    const int warp = tid >> 5;

    float vals[16];
    int cnt = 0;
    float mx = -1e30f;
    for (int i = tid; i < n; i += 256) {
        float v = p[i];
        vals[cnt++] = v;
        mx = fmaxf(mx, v);
    }

    __shared__ float red[8];
    #pragma unroll
    for (int o = 16; o; o >>= 1) mx = fmaxf(mx, __shfl_xor_sync(0xffffffffu, mx, o));
    if (lane == 0) red[warp] = mx;
    __syncthreads();
    float m = -1e30f;
    #pragma unroll
    for (int w = 0; w < 8; w++) m = fmaxf(m, red[w]);
    __syncthreads();

    float sum = 0.f;
    for (int i = 0; i < cnt; i++) {
        vals[i] = __expf(vals[i] - m);
        sum += vals[i];
    }
    #pragma unroll
    for (int o = 16; o; o >>= 1) sum += __shfl_xor_sync(0xffffffffu, sum, o);
    if (lane == 0) red[warp] = sum;
    __syncthreads();
    float tot = 0.f;
    #pragma unroll
    for (int w = 0; w < 8; w++) tot += red[w];
    const float inv = 1.0f / tot;

    cnt = 0;
    for (int i = tid; i < n; i += 256) p[i] = vals[cnt++] * inv;
    for (int i = n + tid; i < ncap; i += 256) p[i] = 0.f;
}

// ---------------------------------------------------------------------------
// Kernel 4: H[b,t,c] = sum_s P[b,t,s] * v[b,s,c]   (s only over causal tiles)
// ---------------------------------------------------------------------------
__global__ __launch_bounds__(256) void k_pv()
{
    const int qt = blockIdx.x;
    const int c0 = blockIdx.y * 64;
    const int b  = blockIdx.z;
    const int t0 = qt * 64;
    const int s_end = (qt + 1) * 64;

    __shared__ float ps[16][65];   // ps[s][t]
    __shared__ float vs[16][64];   // vs[s][c]

    const int tid = threadIdx.x;
    const int row = tid >> 4;      // -> t
    const int col = tid & 15;      // -> c

    float acc[4][4] = {};

    for (int s0 = 0; s0 < s_end; s0 += 16) {
        #pragma unroll
        for (int l = 0; l < 4; l++) {
            int idx = tid + l * 256;
            int tt = idx >> 4, ss = idx & 15;
            ps[ss][tt] = g_s[(size_t)b * TT_DIM * TT_DIM + (size_t)(t0 + tt) * TT_DIM + s0 + ss];
        }
        #pragma unroll
        for (int l = 0; l < 4; l++) {
            int idx = tid + l * 256;
            int ss = idx >> 6, ccx = idx & 63;
            vs[ss][ccx] = g_v[((size_t)b * TT_DIM + s0 + ss) * CC_DIM + c0 + ccx];
        }
        __syncthreads();
        #pragma unroll
        for (int ss = 0; ss < 16; ss++) {
            float pv[4], vv[4];
            #pragma unroll
            for (int i = 0; i < 4; i++) pv[i] = ps[ss][row + i * 16];
            #pragma unroll
            for (int j = 0; j < 4; j++) vv[j] = vs[ss][col + j * 16];
            #pragma unroll
            for (int i = 0; i < 4; i++)
                #pragma unroll
                for (int j = 0; j < 4; j++)
                    acc[i][j] += pv[i] * vv[j];
        }
        __syncthreads();
    }

    #pragma unroll
    for (int i = 0; i < 4; i++) {
        int t = t0 + row + i * 16;
        #pragma unroll
        for (int j = 0; j < 4; j++) {
            int c = c0 + col + j * 16;
            g_h[((size_t)b * TT_DIM + t) * CC_DIM + c] = acc[i][j];
        }
    }
}

// ---------------------------------------------------------------------------
// Kernel 5: out[b,o,t] = x[b,o,t] + sum_c Wp[o,c] * h[b,t,c] + bp[o]
// ---------------------------------------------------------------------------
__global__ __launch_bounds__(256) void k_outproj(
    const float* __restrict__ x,
    const float* __restrict__ Wp,
    const float* __restrict__ bp,
    float* __restrict__ out)
{
    const int t0 = blockIdx.x * 64;
    const int o0 = blockIdx.y * 64;
    const int b  = blockIdx.z;

    __shared__ float hs[16][65];   // hs[c][t]
    __shared__ float ws[16][65];   // ws[c][o]

    const int tid = threadIdx.x;
    const int row = tid >> 4;      // -> o
    const int col = tid & 15;      // -> t

    float acc[4][4] = {};

    for (int c0 = 0; c0 < CC_DIM; c0 += 16) {
        #pragma unroll
        for (int l = 0; l < 4; l++) {
            int idx = tid + l * 256;
            int tt = idx >> 4, cc = idx & 15;
            hs[cc][tt] = g_h[((size_t)b * TT_DIM + t0 + tt) * CC_DIM + c0 + cc];
        }
        #pragma unroll
        for (int l = 0; l < 4; l++) {
            int idx = tid + l * 256;
            int oo = idx >> 4, cc = idx & 15;
            ws[cc][oo] = Wp[(size_t)(o0 + oo) * CC_DIM + c0 + cc];
        }
        __syncthreads();
        #pragma unroll
        for (int cc = 0; cc < 16; cc++) {
            float wv[4], hv[4];
            #pragma unroll
            for (int i = 0; i < 4; i++) wv[i] = ws[cc][row + i * 16];
            #pragma unroll
            for (int j = 0; j < 4; j++) hv[j] = hs[cc][col + j * 16];
            #pragma unroll
            for (int i = 0; i < 4; i++)
                #pragma unroll
                for (int j = 0; j < 4; j++)
                    acc[i][j] += wv[i] * hv[j];
        }
        __syncthreads();
    }

    #pragma unroll
    for (int i = 0; i < 4; i++) {
        int o = o0 + row + i * 16;
        float bias = bp[o];
        #pragma unroll
        for (int j = 0; j < 4; j++) {
            int t = t0 + col + j * 16;
            size_t gi = ((size_t)b * CC_DIM + o) * TT_DIM + t;
            out[gi] = x[gi] + acc[i][j] + bias;
        }
    }
}

// ---------------------------------------------------------------------------
extern "C" void kernel_launch(void* const* d_in, const int* in_sizes, int n_in,
                              void* d_out, int out_size)
{
    const float* x  = (const float*)d_in[0];
    const float* Wq = (const float*)d_in[1];
    const float* bq = (const float*)d_in[2];
    const float* Wk = (const float*)d_in[3];
    const float* bk = (const float*)d_in[4];
    const float* Wv = (const float*)d_in[5];
    const float* bv = (const float*)d_in[6];
    const float* Wp = (const float*)d_in[7];
    const float* bp = (const float*)d_in[8];
    float* out = (float*)d_out;

    dim3 blk(256);
    k_proj   <<<dim3(TT_DIM / 64, CC_DIM / 64, BB * 3), blk>>>(x, Wq, bq, Wk, bk, Wv, bv);
    k_scores <<<dim3(TT_DIM / 64, TT_DIM / 64, BB), blk>>>();
    k_softmax<<<BB * TT_DIM, 256>>>();
    k_pv     <<<dim3(TT_DIM / 64, CC_DIM / 64, BB), blk>>>();
    k_outproj<<<dim3(TT_DIM / 64, CC_DIM / 64, BB), blk>>>(x, Wp, bp, out);
}

// round 3
// speedup vs baseline: 4.3453x; 4.3453x over previous
#include <cuda_runtime.h>
#include <cstdint>

#define BB 4
#define CD 512
#define TD 4096

// ---------------------------------------------------------------------------
// Device scratch
// ---------------------------------------------------------------------------
__device__ float g_xT[(size_t)BB * TD * CD];   // x transposed: [B][T][C]
__device__ float g_q [(size_t)BB * TD * CD];   // [B][T][C]
__device__ float g_k [(size_t)BB * TD * CD];   // [B][T][C]
__device__ float g_vT[(size_t)BB * TD * CD];   // [B][C][T]
__device__ float g_h [(size_t)BB * TD * CD];   // [B][T][C]
__device__ float g_s [(size_t)BB * TD * TD];   // [B][T][T] scores / probs

// ---------------------------------------------------------------------------
// Helpers (base sm_103 target only: mma.sync + cp.async, no tcgen05)
// ---------------------------------------------------------------------------
__device__ __forceinline__ uint32_t smem_u32(const void* p) {
    uint32_t a;
    asm("{ .reg .u64 t; cvta.to.shared.u64 t, %1; cvt.u32.u64 %0, t; }"
        : "=r"(a) : "l"(p));
    return a;
}

__device__ __forceinline__ void cpa16(uint32_t dst, const float* src) {
    asm volatile("cp.async.cg.shared.global [%0], [%1], 16;"
                 :: "r"(dst), "l"(src));
}
#define CP_COMMIT() asm volatile("cp.async.commit_group;" ::: "memory")
#define CP_WAIT(N)  asm volatile("cp.async.wait_group %0;" :: "n"(N) : "memory")

// D += A(16x8) * B(8x8), tf32 in, fp32 accum
__device__ __forceinline__ void mma8(float* c, const uint32_t* a, const uint32_t* b) {
    asm volatile(
        "mma.sync.aligned.m16n8k8.row.col.f32.tf32.tf32.f32 "
        "{%0,%1,%2,%3}, {%4,%5,%6,%7}, {%8,%9}, {%0,%1,%2,%3};"
        : "+f"(c[0]), "+f"(c[1]), "+f"(c[2]), "+f"(c[3])
        : "r"(a[0]), "r"(a[1]), "r"(a[2]), "r"(a[3]),
          "r"(b[0]), "r"(b[1]));
}

// ---------------------------------------------------------------------------
// Tile config
// ---------------------------------------------------------------------------
#define BM 128
#define BN 128
#define BK 32
#define PAD 36           // smem row pitch in floats (conflict-free; 144B, 16B-aligned)
#define ATT_SCALE 0.044194173824159216f  // 1/sqrt(512)

#define SMEM_FLOATS (4 * BM * PAD)       // 2 bufs x (A + B) tiles
#define SMEM_BYTES  (SMEM_FLOATS * 4)    // 73728

// MODE: 0 = D=A.B^T + bias[n]          (q,k projection)
//       1 = D=A.B^T + bias[m]          (v projection, transposed output)
//       2 = D=A.B^T + bias[m] + resid  (out projection)
//       3 = D=A.B^T * scale, causal tile skip (scores)
//       4 = D=A.B^T, K = (mb+1)*128    (PV)
template <int MODE>
__global__ __launch_bounds__(256) void gemm_mma(
    const float* __restrict__ A, const float* __restrict__ B, float* __restrict__ D,
    const float* __restrict__ bias, const float* __restrict__ resid,
    long lda, long ldb, long ldd, long sA, long sB, long sD, int Kparam)
{
    const int nb = blockIdx.x, mb = blockIdx.y, bz = blockIdx.z;
    if (MODE == 3 && nb > mb) return;   // causal tile skip

    const int n0 = nb * BN, m0 = mb * BM;
    const int K = (MODE == 4) ? (mb + 1) * BM : Kparam;
    const int nst = K / BK;

    A += (size_t)bz * sA;
    B += (size_t)bz * sB;
    D += (size_t)bz * sD;
    const float* R = (MODE == 2) ? (resid + (size_t)bz * sD) : nullptr;

    extern __shared__ float sm[];
    // As[buf][m][k], Bs[buf][n][k]
    float (*As)[BM][PAD] = (float(*)[BM][PAD])sm;
    float (*Bs)[BM][PAD] = (float(*)[BM][PAD])(sm + 2 * BM * PAD);

    const int tid  = threadIdx.x;
    const int wid  = tid >> 5;
    const int lane = tid & 31;
    const int g    = lane >> 2;      // group id (0..7)
    const int tg   = lane & 3;       // thread in group
    const int wm   = (wid >> 2) * 64;  // warp m offset in tile
    const int wn   = (wid & 3) * 32;   // warp n offset in tile

    const int ldr = tid >> 3;        // load row (0..31 per iter)
    const int ldq = tid & 7;         // float4 index in row

    float acc[4][4][4] = {};

    // ---- prefetch tile 0 -------------------------------------------------
    {
        const int k0 = 0;
        #pragma unroll
        for (int i = 0; i < 4; i++) {
            int r = ldr + i * 32;
            cpa16(smem_u32(&As[0][r][ldq * 4]), A + (size_t)(m0 + r) * lda + k0 + ldq * 4);
            cpa16(smem_u32(&Bs[0][r][ldq * 4]), B + (size_t)(n0 + r) * ldb + k0 + ldq * 4);
        }
        CP_COMMIT();
    }

    for (int st = 0; st < nst; st++) {
        const int buf = st & 1;
        if (st + 1 < nst) {
            const int k0 = (st + 1) * BK;
            const int nbuf = buf ^ 1;
            #pragma unroll
            for (int i = 0; i < 4; i++) {
                int r = ldr + i * 32;
                cpa16(smem_u32(&As[nbuf][r][ldq * 4]), A + (size_t)(m0 + r) * lda + k0 + ldq * 4);
                cpa16(smem_u32(&Bs[nbuf][r][ldq * 4]), B + (size_t)(n0 + r) * ldb + k0 + ldq * 4);
            }
            CP_COMMIT();
            CP_WAIT(1);
        } else {
            CP_WAIT(0);
        }
        __syncthreads();

        #pragma unroll
        for (int k8 = 0; k8 < BK / 8; k8++) {
            const int kk = k8 * 8;
            uint32_t af[4][4], bf[4][2];
            #pragma unroll
            for (int mt = 0; mt < 4; mt++) {
                const float* ap = &As[buf][wm + mt * 16 + g][kk + tg];
                af[mt][0] = __float_as_uint(ap[0]);
                af[mt][1] = __float_as_uint(ap[8 * PAD]);
                af[mt][2] = __float_as_uint(ap[4]);
                af[mt][3] = __float_as_uint(ap[8 * PAD + 4]);
            }
            #pragma unroll
            for (int nt = 0; nt < 4; nt++) {
                const float* bp = &Bs[buf][wn + nt * 8 + g][kk + tg];
                bf[nt][0] = __float_as_uint(bp[0]);
                bf[nt][1] = __float_as_uint(bp[4]);
            }
            #pragma unroll
            for (int mt = 0; mt < 4; mt++)
                #pragma unroll
                for (int nt = 0; nt < 4; nt++)
                    mma8(acc[mt][nt], af[mt], bf[nt]);
        }
        __syncthreads();
    }

    // ---- epilogue ---------------------------------------------------------
    #pragma unroll
    for (int mt = 0; mt < 4; mt++) {
        const int r0 = m0 + wm + mt * 16 + g;
        const int r1 = r0 + 8;
        float bm0 = 0.f, bm1 = 0.f;
        if (MODE == 1 || MODE == 2) { bm0 = bias[r0]; bm1 = bias[r1]; }
        #pragma unroll
        for (int nt = 0; nt < 4; nt++) {
            const int cc = n0 + wn + nt * 8 + tg * 2;
            float v00 = acc[mt][nt][0], v01 = acc[mt][nt][1];
            float v10 = acc[mt][nt][2], v11 = acc[mt][nt][3];
            if (MODE == 0) {
                float b0 = bias[cc], b1 = bias[cc + 1];
                v00 += b0; v01 += b1; v10 += b0; v11 += b1;
            }
            if (MODE == 1 || MODE == 2) {
                v00 += bm0; v01 += bm0; v10 += bm1; v11 += bm1;
            }
            if (MODE == 3) {
                v00 *= ATT_SCALE; v01 *= ATT_SCALE; v10 *= ATT_SCALE; v11 *= ATT_SCALE;
            }
            if (MODE == 2) {
                float2 x0 = *(const float2*)(R + (size_t)r0 * ldd + cc);
                float2 x1 = *(const float2*)(R + (size_t)r1 * ldd + cc);
                v00 += x0.x; v01 += x0.y; v10 += x1.x; v11 += x1.y;
            }
            *(float2*)(D + (size_t)r0 * ldd + cc) = make_float2(v00, v01);
            *(float2*)(D + (size_t)r1 * ldd + cc) = make_float2(v10, v11);
        }
    }
}

// ---------------------------------------------------------------------------
// Transpose: x[b,c,t] -> xT[b,t,c]
// ---------------------------------------------------------------------------
__global__ __launch_bounds__(256) void k_transpose(const float* __restrict__ x,
                                                   float* __restrict__ xT)
{
    __shared__ float tile[32][33];
    const int b  = blockIdx.z;
    const int t0 = blockIdx.x * 32;
    const int c0 = blockIdx.y * 32;
    const int tx = threadIdx.x, ty = threadIdx.y;

    #pragma unroll
    for (int i = ty; i < 32; i += 8)
        tile[i][tx] = x[((size_t)b * CD + c0 + i) * TD + t0 + tx];   // tile[c][t]
    __syncthreads();
    #pragma unroll
    for (int i = ty; i < 32; i += 8)
        xT[((size_t)b * TD + t0 + i) * CD + c0 + tx] = tile[tx][i];
}

// ---------------------------------------------------------------------------
// Row softmax over s in [0, t]; zero-fill (t, next multiple of 128)
// ---------------------------------------------------------------------------
__global__ __launch_bounds__(256) void k_softmax()
{
    const int b = blockIdx.x / TD;
    const int t = blockIdx.x % TD;
    float* p = g_s + (size_t)b * TD * TD + (size_t)t * TD;
    const int n    = t + 1;
    const int ncap = ((t >> 7) + 1) << 7;

    const int tid  = threadIdx.x;
    const int lane = tid & 31;
    const int warp = tid >> 5;

    float vals[16];
    int cnt = 0;
    float mx = -1e30f;
    for (int i = tid; i < n; i += 256) {
        float v = p[i];
        vals[cnt++] = v;
        mx = fmaxf(mx, v);
    }

    __shared__ float red[8];
    #pragma unroll
    for (int o = 16; o; o >>= 1) mx = fmaxf(mx, __shfl_xor_sync(0xffffffffu, mx, o));
    if (lane == 0) red[warp] = mx;
    __syncthreads();
    float m = -1e30f;
    #pragma unroll
    for (int w = 0; w < 8; w++) m = fmaxf(m, red[w]);
    __syncthreads();

    float sum = 0.f;
    for (int i = 0; i < cnt; i++) {
        vals[i] = __expf(vals[i] - m);
        sum += vals[i];
    }
    #pragma unroll
    for (int o = 16; o; o >>= 1) sum += __shfl_xor_sync(0xffffffffu, sum, o);
    if (lane == 0) red[warp] = sum;
    __syncthreads();
    float tot = 0.f;
    #pragma unroll
    for (int w = 0; w < 8; w++) tot += red[w];
    const float inv = 1.0f / tot;

    cnt = 0;
    for (int i = tid; i < n; i += 256) p[i] = vals[cnt++] * inv;
    for (int i = n + tid; i < ncap; i += 256) p[i] = 0.f;
}

// ---------------------------------------------------------------------------
extern "C" void kernel_launch(void* const* d_in, const int* in_sizes, int n_in,
                              void* d_out, int out_size)
{
    const float* x  = (const float*)d_in[0];
    const float* Wq = (const float*)d_in[1];
    const float* bq = (const float*)d_in[2];
    const float* Wk = (const float*)d_in[3];
    const float* bk = (const float*)d_in[4];
    const float* Wv = (const float*)d_in[5];
    const float* bv = (const float*)d_in[6];
    const float* Wp = (const float*)d_in[7];
    const float* bp = (const float*)d_in[8];
    float* out = (float*)d_out;

    float *xT, *q, *k, *vT, *h, *s;
    cudaGetSymbolAddress((void**)&xT, g_xT);
    cudaGetSymbolAddress((void**)&q,  g_q);
    cudaGetSymbolAddress((void**)&k,  g_k);
    cudaGetSymbolAddress((void**)&vT, g_vT);
    cudaGetSymbolAddress((void**)&h,  g_h);
    cudaGetSymbolAddress((void**)&s,  g_s);

    const long TC = (long)TD * CD;
    const long SS = (long)TD * TD;

    cudaFuncSetAttribute(gemm_mma<0>, cudaFuncAttributeMaxDynamicSharedMemorySize, SMEM_BYTES);
    cudaFuncSetAttribute(gemm_mma<1>, cudaFuncAttributeMaxDynamicSharedMemorySize, SMEM_BYTES);
    cudaFuncSetAttribute(gemm_mma<2>, cudaFuncAttributeMaxDynamicSharedMemorySize, SMEM_BYTES);
    cudaFuncSetAttribute(gemm_mma<3>, cudaFuncAttributeMaxDynamicSharedMemorySize, SMEM_BYTES);
    cudaFuncSetAttribute(gemm_mma<4>, cudaFuncAttributeMaxDynamicSharedMemorySize, SMEM_BYTES);

    // 1) transpose x -> xT [B][T][C]
    k_transpose<<<dim3(TD / 32, CD / 32, BB), dim3(32, 8)>>>(x, xT);

    // 2) q = xT . Wq^T + bq ; k likewise       D[t][o], bias by col
    gemm_mma<0><<<dim3(CD / BN, TD / BM, BB), 256, SMEM_BYTES>>>(
        xT, Wq, q, bq, nullptr, CD, CD, CD, TC, 0, TC, CD);
    gemm_mma<0><<<dim3(CD / BN, TD / BM, BB), 256, SMEM_BYTES>>>(
        xT, Wk, k, bk, nullptr, CD, CD, CD, TC, 0, TC, CD);

    // 3) vT = Wv . xT^T + bv  -> [C][T], bias by row
    gemm_mma<1><<<dim3(TD / BN, CD / BM, BB), 256, SMEM_BYTES>>>(
        Wv, xT, vT, bv, nullptr, CD, CD, TD, 0, TC, TC, CD);

    // 4) scores: S[t][s] = scale * q.k^T (causal tiles only)
    gemm_mma<3><<<dim3(TD / BN, TD / BM, BB), 256, SMEM_BYTES>>>(
        q, k, s, nullptr, nullptr, CD, CD, TD, TC, TC, SS, CD);

    // 5) softmax rows (zero-pads to 128-grain for PV)
    k_softmax<<<BB * TD, 256>>>();

    // 6) h = P . vT^T   D[t][c], K variable = (mb+1)*128
    gemm_mma<4><<<dim3(CD / BN, TD / BM, BB), 256, SMEM_BYTES>>>(
        s, vT, h, nullptr, nullptr, TD, TD, CD, SS, TC, TC, 0);

    // 7) out = Wp . h^T + bp + x   D[o][t], bias by row, residual
    gemm_mma<2><<<dim3(TD / BN, CD / BM, BB), 256, SMEM_BYTES>>>(
        Wp, h, out, bp, x, CD, CD, TD, 0, TC, TC, CD);
}

// round 4
// speedup vs baseline: 4.5569x; 1.0487x over previous
#include <cuda_runtime.h>
#include <cstdint>

#define BB 4
#define CD 512
#define TD 4096

// ---------------------------------------------------------------------------
// Device scratch
// ---------------------------------------------------------------------------
__device__ float g_xT[(size_t)BB * TD * CD];   // x transposed: [B][T][C]
__device__ float g_q [(size_t)BB * TD * CD];   // [B][T][C]
__device__ float g_k [(size_t)BB * TD * CD];   // [B][T][C]
__device__ float g_vT[(size_t)BB * TD * CD];   // [B][C][T]
__device__ float g_h [(size_t)BB * TD * CD];   // [B][T][C]
__device__ float g_s [(size_t)BB * TD * TD];   // [B][T][T] scores / probs

// ---------------------------------------------------------------------------
// Helpers (base sm_103 target only: mma.sync + cp.async, no tcgen05)
// ---------------------------------------------------------------------------
__device__ __forceinline__ uint32_t smem_u32(const void* p) {
    uint32_t a;
    asm("{ .reg .u64 t; cvta.to.shared.u64 t, %1; cvt.u32.u64 %0, t; }"
        : "=r"(a) : "l"(p));
    return a;
}

__device__ __forceinline__ void cpa16(uint32_t dst, const float* src) {
    asm volatile("cp.async.cg.shared.global [%0], [%1], 16;"
                 :: "r"(dst), "l"(src));
}
#define CP_COMMIT() asm volatile("cp.async.commit_group;" ::: "memory")
#define CP_WAIT(N)  asm volatile("cp.async.wait_group %0;" :: "n"(N) : "memory")

// D += A(16x8) * B(8x8), tf32 in, fp32 accum
__device__ __forceinline__ void mma8(float* c, const uint32_t* a, const uint32_t* b) {
    asm volatile(
        "mma.sync.aligned.m16n8k8.row.col.f32.tf32.tf32.f32 "
        "{%0,%1,%2,%3}, {%4,%5,%6,%7}, {%8,%9}, {%0,%1,%2,%3};"
        : "+f"(c[0]), "+f"(c[1]), "+f"(c[2]), "+f"(c[3])
        : "r"(a[0]), "r"(a[1]), "r"(a[2]), "r"(a[3]),
          "r"(b[0]), "r"(b[1]));
}

// ---------------------------------------------------------------------------
// Tile config
// ---------------------------------------------------------------------------
#define BM 128
#define BN 128
#define BK 32
#define PAD 36           // smem row pitch in floats (conflict-free; 144B, 16B-aligned)
#define ATT_SCALE 0.044194173824159216f  // 1/sqrt(512)

#define SMEM_FLOATS (4 * BM * PAD)       // 2 bufs x (A + B) tiles
#define SMEM_BYTES  (SMEM_FLOATS * 4)    // 73728 (x2 CTAs = 147456 <= 228KB)

// MODE: 0 = D=A.B^T + bias[n]          (q,k projection)
//       1 = D=A.B^T + bias[m]          (v projection, transposed output)
//       2 = D=A.B^T + bias[m] + resid  (out projection)
//       3 = D=A.B^T * scale, causal tile skip (scores)
//       4 = D=A.B^T, K = (mb+1)*128    (PV)
template <int MODE>
__global__ __launch_bounds__(256, 2) void gemm_mma(
    const float* __restrict__ A, const float* __restrict__ B, float* __restrict__ D,
    const float* __restrict__ bias, const float* __restrict__ resid,
    long lda, long ldb, long ldd, long sA, long sB, long sD, int Kparam)
{
    const int nb = blockIdx.x, bz = blockIdx.z;
    // For variable-K / causal kernels, launch biggest-K blocks first.
    const int mb = (MODE == 3 || MODE == 4) ? (gridDim.y - 1 - blockIdx.y)
                                            : blockIdx.y;
    if (MODE == 3 && nb > mb) return;   // causal tile skip

    const int n0 = nb * BN, m0 = mb * BM;
    const int K = (MODE == 4) ? (mb + 1) * BM : Kparam;
    const int nst = K / BK;

    A += (size_t)bz * sA;
    B += (size_t)bz * sB;
    D += (size_t)bz * sD;
    const float* R = (MODE == 2) ? (resid + (size_t)bz * sD) : nullptr;

    extern __shared__ float sm[];
    // As[buf][m][k], Bs[buf][n][k]
    float (*As)[BM][PAD] = (float(*)[BM][PAD])sm;
    float (*Bs)[BM][PAD] = (float(*)[BM][PAD])(sm + 2 * BM * PAD);

    const int tid  = threadIdx.x;
    const int wid  = tid >> 5;
    const int lane = tid & 31;
    const int g    = lane >> 2;      // group id (0..7)
    const int tg   = lane & 3;       // thread in group
    const int wm   = (wid >> 2) * 64;  // warp m offset in tile
    const int wn   = (wid & 3) * 32;   // warp n offset in tile

    const int ldr = tid >> 3;        // load row (0..31 per iter)
    const int ldq = tid & 7;         // float4 index in row

    float acc[4][4][4] = {};

    // ---- prefetch tile 0 -------------------------------------------------
    {
        #pragma unroll
        for (int i = 0; i < 4; i++) {
            int r = ldr + i * 32;
            cpa16(smem_u32(&As[0][r][ldq * 4]), A + (size_t)(m0 + r) * lda + ldq * 4);
            cpa16(smem_u32(&Bs[0][r][ldq * 4]), B + (size_t)(n0 + r) * ldb + ldq * 4);
        }
        CP_COMMIT();
    }

    for (int st = 0; st < nst; st++) {
        const int buf = st & 1;
        if (st + 1 < nst) {
            const int k0 = (st + 1) * BK;
            const int nbuf = buf ^ 1;
            #pragma unroll
            for (int i = 0; i < 4; i++) {
                int r = ldr + i * 32;
                cpa16(smem_u32(&As[nbuf][r][ldq * 4]), A + (size_t)(m0 + r) * lda + k0 + ldq * 4);
                cpa16(smem_u32(&Bs[nbuf][r][ldq * 4]), B + (size_t)(n0 + r) * ldb + k0 + ldq * 4);
            }
            CP_COMMIT();
            CP_WAIT(1);
        } else {
            CP_WAIT(0);
        }
        __syncthreads();

        #pragma unroll
        for (int k8 = 0; k8 < BK / 8; k8++) {
            const int kk = k8 * 8;
            uint32_t af[4][4], bf[4][2];
            #pragma unroll
            for (int mt = 0; mt < 4; mt++) {
                const float* ap = &As[buf][wm + mt * 16 + g][kk + tg];
                af[mt][0] = __float_as_uint(ap[0]);
                af[mt][1] = __float_as_uint(ap[8 * PAD]);
                af[mt][2] = __float_as_uint(ap[4]);
                af[mt][3] = __float_as_uint(ap[8 * PAD + 4]);
            }
            #pragma unroll
            for (int nt = 0; nt < 4; nt++) {
                const float* bp = &Bs[buf][wn + nt * 8 + g][kk + tg];
                bf[nt][0] = __float_as_uint(bp[0]);
                bf[nt][1] = __float_as_uint(bp[4]);
            }
            #pragma unroll
            for (int mt = 0; mt < 4; mt++)
                #pragma unroll
                for (int nt = 0; nt < 4; nt++)
                    mma8(acc[mt][nt], af[mt], bf[nt]);
        }
        __syncthreads();
    }

    // ---- epilogue ---------------------------------------------------------
    #pragma unroll
    for (int mt = 0; mt < 4; mt++) {
        const int r0 = m0 + wm + mt * 16 + g;
        const int r1 = r0 + 8;
        float bm0 = 0.f, bm1 = 0.f;
        if (MODE == 1 || MODE == 2) { bm0 = bias[r0]; bm1 = bias[r1]; }
        #pragma unroll
        for (int nt = 0; nt < 4; nt++) {
            const int cc = n0 + wn + nt * 8 + tg * 2;
            float v00 = acc[mt][nt][0], v01 = acc[mt][nt][1];
            float v10 = acc[mt][nt][2], v11 = acc[mt][nt][3];
            if (MODE == 0) {
                float b0 = bias[cc], b1 = bias[cc + 1];
                v00 += b0; v01 += b1; v10 += b0; v11 += b1;
            }
            if (MODE == 1 || MODE == 2) {
                v00 += bm0; v01 += bm0; v10 += bm1; v11 += bm1;
            }
            if (MODE == 3) {
                v00 *= ATT_SCALE; v01 *= ATT_SCALE; v10 *= ATT_SCALE; v11 *= ATT_SCALE;
            }
            if (MODE == 2) {
                float2 x0 = *(const float2*)(R + (size_t)r0 * ldd + cc);
                float2 x1 = *(const float2*)(R + (size_t)r1 * ldd + cc);
                v00 += x0.x; v01 += x0.y; v10 += x1.x; v11 += x1.y;
            }
            *(float2*)(D + (size_t)r0 * ldd + cc) = make_float2(v00, v01);
            *(float2*)(D + (size_t)r1 * ldd + cc) = make_float2(v10, v11);
        }
    }
}

// ---------------------------------------------------------------------------
// Transpose: x[b,c,t] -> xT[b,t,c]
// ---------------------------------------------------------------------------
__global__ __launch_bounds__(256) void k_transpose(const float* __restrict__ x,
                                                   float* __restrict__ xT)
{
    __shared__ float tile[32][33];
    const int b  = blockIdx.z;
    const int t0 = blockIdx.x * 32;
    const int c0 = blockIdx.y * 32;
    const int tx = threadIdx.x, ty = threadIdx.y;

    #pragma unroll
    for (int i = ty; i < 32; i += 8)
        tile[i][tx] = x[((size_t)b * CD + c0 + i) * TD + t0 + tx];   // tile[c][t]
    __syncthreads();
    #pragma unroll
    for (int i = ty; i < 32; i += 8)
        xT[((size_t)b * TD + t0 + i) * CD + c0 + tx] = tile[tx][i];
}

// ---------------------------------------------------------------------------
// Row softmax over s in [0, t]; zero-fill (t, next multiple of 128)
// ---------------------------------------------------------------------------
__global__ __launch_bounds__(256) void k_softmax()
{
    const int b = blockIdx.x / TD;
    const int t = blockIdx.x % TD;
    float* p = g_s + (size_t)b * TD * TD + (size_t)t * TD;
    const int n    = t + 1;
    const int ncap = ((t >> 7) + 1) << 7;

    const int tid  = threadIdx.x;
    const int lane = tid & 31;
    const int warp = tid >> 5;

    float vals[16];
    int cnt = 0;
    float mx = -1e30f;
    for (int i = tid; i < n; i += 256) {
        float v = p[i];
        vals[cnt++] = v;
        mx = fmaxf(mx, v);
    }

    __shared__ float red[8];
    #pragma unroll
    for (int o = 16; o; o >>= 1) mx = fmaxf(mx, __shfl_xor_sync(0xffffffffu, mx, o));
    if (lane == 0) red[warp] = mx;
    __syncthreads();
    float m = -1e30f;
    #pragma unroll
    for (int w = 0; w < 8; w++) m = fmaxf(m, red[w]);
    __syncthreads();

    float sum = 0.f;
    for (int i = 0; i < cnt; i++) {
        vals[i] = __expf(vals[i] - m);
        sum += vals[i];
    }
    #pragma unroll
    for (int o = 16; o; o >>= 1) sum += __shfl_xor_sync(0xffffffffu, sum, o);
    if (lane == 0) red[warp] = sum;
    __syncthreads();
    float tot = 0.f;
    #pragma unroll
    for (int w = 0; w < 8; w++) tot += red[w];
    const float inv = 1.0f / tot;

    cnt = 0;
    for (int i = tid; i < n; i += 256) p[i] = vals[cnt++] * inv;
    for (int i = n + tid; i < ncap; i += 256) p[i] = 0.f;
}

// ---------------------------------------------------------------------------
extern "C" void kernel_launch(void* const* d_in, const int* in_sizes, int n_in,
                              void* d_out, int out_size)
{
    const float* x  = (const float*)d_in[0];
    const float* Wq = (const float*)d_in[1];
    const float* bq = (const float*)d_in[2];
    const float* Wk = (const float*)d_in[3];
    const float* bk = (const float*)d_in[4];
    const float* Wv = (const float*)d_in[5];
    const float* bv = (const float*)d_in[6];
    const float* Wp = (const float*)d_in[7];
    const float* bp = (const float*)d_in[8];
    float* out = (float*)d_out;

    float *xT, *q, *k, *vT, *h, *s;
    cudaGetSymbolAddress((void**)&xT, g_xT);
    cudaGetSymbolAddress((void**)&q,  g_q);
    cudaGetSymbolAddress((void**)&k,  g_k);
    cudaGetSymbolAddress((void**)&vT, g_vT);
    cudaGetSymbolAddress((void**)&h,  g_h);
    cudaGetSymbolAddress((void**)&s,  g_s);

    const long TC = (long)TD * CD;
    const long SS = (long)TD * TD;

    cudaFuncSetAttribute(gemm_mma<0>, cudaFuncAttributeMaxDynamicSharedMemorySize, SMEM_BYTES);
    cudaFuncSetAttribute(gemm_mma<1>, cudaFuncAttributeMaxDynamicSharedMemorySize, SMEM_BYTES);
    cudaFuncSetAttribute(gemm_mma<2>, cudaFuncAttributeMaxDynamicSharedMemorySize, SMEM_BYTES);
    cudaFuncSetAttribute(gemm_mma<3>, cudaFuncAttributeMaxDynamicSharedMemorySize, SMEM_BYTES);
    cudaFuncSetAttribute(gemm_mma<4>, cudaFuncAttributeMaxDynamicSharedMemorySize, SMEM_BYTES);

    // 1) transpose x -> xT [B][T][C]
    k_transpose<<<dim3(TD / 32, CD / 32, BB), dim3(32, 8)>>>(x, xT);

    // 2) q = xT . Wq^T + bq ; k likewise       D[t][o], bias by col
    gemm_mma<0><<<dim3(CD / BN, TD / BM, BB), 256, SMEM_BYTES>>>(
        xT, Wq, q, bq, nullptr, CD, CD, CD, TC, 0, TC, CD);
    gemm_mma<0><<<dim3(CD / BN, TD / BM, BB), 256, SMEM_BYTES>>>(
        xT, Wk, k, bk, nullptr, CD, CD, CD, TC, 0, TC, CD);

    // 3) vT = Wv . xT^T + bv  -> [C][T], bias by row
    gemm_mma<1><<<dim3(TD / BN, CD / BM, BB), 256, SMEM_BYTES>>>(
        Wv, xT, vT, bv, nullptr, CD, CD, TD, 0, TC, TC, CD);

    // 4) scores: S[t][s] = scale * q.k^T (causal tiles only)
    gemm_mma<3><<<dim3(TD / BN, TD / BM, BB), 256, SMEM_BYTES>>>(
        q, k, s, nullptr, nullptr, CD, CD, TD, TC, TC, SS, CD);

    // 5) softmax rows (zero-pads to 128-grain for PV)
    k_softmax<<<BB * TD, 256>>>();

    // 6) h = P . vT^T   D[t][c], K variable = (mb+1)*128
    gemm_mma<4><<<dim3(CD / BN, TD / BM, BB), 256, SMEM_BYTES>>>(
        s, vT, h, nullptr, nullptr, TD, TD, CD, SS, TC, TC, 0);

    // 7) out = Wp . h^T + bp + x   D[o][t], bias by row, residual
    gemm_mma<2><<<dim3(TD / BN, CD / BM, BB), 256, SMEM_BYTES>>>(
        Wp, h, out, bp, x, CD, CD, TD, 0, TC, TC, CD);
}

// round 5
// speedup vs baseline: 4.7299x; 1.0380x over previous
#include <cuda_runtime.h>
#include <cstdint>

#define BB 4
#define CD 512
#define TD 4096

// ---------------------------------------------------------------------------
// Device scratch
// ---------------------------------------------------------------------------
__device__ float g_xT[(size_t)BB * TD * CD];   // x transposed: [B][T][C]
__device__ float g_q [(size_t)BB * TD * CD];   // [B][T][C]
__device__ float g_k [(size_t)BB * TD * CD];   // [B][T][C]
__device__ float g_vT[(size_t)BB * TD * CD];   // [B][C][T]
__device__ float g_h [(size_t)BB * TD * CD];   // [B][T][C]
__device__ float g_s [(size_t)BB * TD * TD];   // [B][T][T] scores / probs

// ---------------------------------------------------------------------------
// Helpers (base sm_103 target: mma.sync + cp.async + ldmatrix, no tcgen05)
// ---------------------------------------------------------------------------
__device__ __forceinline__ uint32_t smem_u32(const void* p) {
    uint32_t a;
    asm("{ .reg .u64 t; cvta.to.shared.u64 t, %1; cvt.u32.u64 %0, t; }"
        : "=r"(a) : "l"(p));
    return a;
}

__device__ __forceinline__ void cpa16(uint32_t dst, const float* src) {
    asm volatile("cp.async.cg.shared.global [%0], [%1], 16;"
                 :: "r"(dst), "l"(src));
}
#define CP_COMMIT() asm volatile("cp.async.commit_group;" ::: "memory")
#define CP_WAIT(N)  asm volatile("cp.async.wait_group %0;" :: "n"(N) : "memory")

// ldmatrix x4: four 8x8 b16 tiles (== four 8x4 tf32 tiles)
#define LDSM4(r0, r1, r2, r3, addr) \
    asm volatile("ldmatrix.sync.aligned.m8n8.x4.shared.b16 {%0,%1,%2,%3}, [%4];" \
                 : "=r"(r0), "=r"(r1), "=r"(r2), "=r"(r3) : "r"(addr))

// D += A(16x8) * B(8x8), tf32 in, fp32 accum
__device__ __forceinline__ void mma8(float* c, const uint32_t* a, const uint32_t* b) {
    asm volatile(
        "mma.sync.aligned.m16n8k8.row.col.f32.tf32.tf32.f32 "
        "{%0,%1,%2,%3}, {%4,%5,%6,%7}, {%8,%9}, {%0,%1,%2,%3};"
        : "+f"(c[0]), "+f"(c[1]), "+f"(c[2]), "+f"(c[3])
        : "r"(a[0]), "r"(a[1]), "r"(a[2]), "r"(a[3]),
          "r"(b[0]), "r"(b[1]));
}

// ---------------------------------------------------------------------------
// Tile config
// ---------------------------------------------------------------------------
#define BM 128
#define BN 128
#define BK 32
#define PAD 36           // row pitch in floats; 9x16B granules -> LDSM conflict-free
#define ATT_SCALE 0.044194173824159216f  // 1/sqrt(512)

#define SMEM_FLOATS (4 * BM * PAD)       // 2 bufs x (A + B) tiles
#define SMEM_BYTES  (SMEM_FLOATS * 4)    // 73728 (x2 CTAs <= 228KB)
#define BUF_STRIDE  (BM * PAD * 4)       // bytes per buffer per operand

// MODE: 0 = D=A.B^T + bias[n]          (q,k projection)
//       1 = D=A.B^T + bias[m]          (v projection, transposed output)
//       2 = D=A.B^T + bias[m] + resid  (out projection)
//       3 = D=A.B^T * scale, causal tile skip (scores)
//       4 = D=A.B^T, K = (mb+1)*128    (PV)
template <int MODE>
__global__ __launch_bounds__(256, 2) void gemm_mma(
    const float* __restrict__ A, const float* __restrict__ B, float* __restrict__ D,
    const float* __restrict__ bias, const float* __restrict__ resid,
    long lda, long ldb, long ldd, long sA, long sB, long sD, int Kparam)
{
    const int nb = blockIdx.x, bz = blockIdx.z;
    const int mb = (MODE == 3 || MODE == 4) ? (gridDim.y - 1 - blockIdx.y)
                                            : blockIdx.y;
    if (MODE == 3 && nb > mb) return;   // causal tile skip

    const int n0 = nb * BN, m0 = mb * BM;
    const int K = (MODE == 4) ? (mb + 1) * BM : Kparam;
    const int nst = K / BK;

    A += (size_t)bz * sA;
    B += (size_t)bz * sB;
    D += (size_t)bz * sD;
    const float* R = (MODE == 2) ? (resid + (size_t)bz * sD) : nullptr;

    extern __shared__ float sm[];
    float (*As)[BM][PAD] = (float(*)[BM][PAD])sm;
    float (*Bs)[BM][PAD] = (float(*)[BM][PAD])(sm + 2 * BM * PAD);

    const int tid  = threadIdx.x;
    const int wid  = tid >> 5;
    const int lane = tid & 31;
    const int g    = lane >> 2;
    const int tg   = lane & 3;
    const int wm   = (wid >> 2) * 64;  // warp m offset in tile
    const int wn   = (wid & 3) * 32;   // warp n offset in tile

    const int ldr = tid >> 3;          // load row
    const int ldq = tid & 7;           // float4 index in row

    // ---- ldmatrix per-lane byte offsets (within one operand buffer) -------
    const int lr = lane & 7;           // row within 8-row tile
    const int lt = lane >> 3;          // tile index 0..3
    const uint32_t uAs = smem_u32(sm);
    const uint32_t uBs = uAs + 2u * BUF_STRIDE;

    uint32_t aOff[4], bOff[2];
    #pragma unroll
    for (int mt = 0; mt < 4; mt++) {
        // x4 tiles: t0=rows0-7/k0-3, t1=rows8-15/k0-3, t2=rows0-7/k4-7, t3=rows8-15/k4-7
        int row = wm + mt * 16 + (lt & 1) * 8 + lr;
        int col = (lt >> 1) * 4;
        aOff[mt] = (uint32_t)(row * PAD + col) * 4u;
    }
    #pragma unroll
    for (int p = 0; p < 2; p++) {
        // x4 tiles: t0=nt(2p) k0-3, t1=nt(2p) k4-7, t2=nt(2p+1) k0-3, t3=nt(2p+1) k4-7
        int row = wn + p * 16 + (lt >> 1) * 8 + lr;
        int col = (lt & 1) * 4;
        bOff[p] = (uint32_t)(row * PAD + col) * 4u;
    }

    float acc[4][4][4] = {};

    // ---- prefetch tile 0 ---------------------------------------------------
    {
        #pragma unroll
        for (int i = 0; i < 4; i++) {
            int r = ldr + i * 32;
            cpa16(smem_u32(&As[0][r][ldq * 4]), A + (size_t)(m0 + r) * lda + ldq * 4);
            cpa16(smem_u32(&Bs[0][r][ldq * 4]), B + (size_t)(n0 + r) * ldb + ldq * 4);
        }
        CP_COMMIT();
    }

    for (int st = 0; st < nst; st++) {
        const int buf = st & 1;
        if (st + 1 < nst) {
            const int k0 = (st + 1) * BK;
            const int nbuf = buf ^ 1;
            #pragma unroll
            for (int i = 0; i < 4; i++) {
                int r = ldr + i * 32;
                cpa16(smem_u32(&As[nbuf][r][ldq * 4]), A + (size_t)(m0 + r) * lda + k0 + ldq * 4);
                cpa16(smem_u32(&Bs[nbuf][r][ldq * 4]), B + (size_t)(n0 + r) * ldb + k0 + ldq * 4);
            }
            CP_COMMIT();
            CP_WAIT(1);
        } else {
            CP_WAIT(0);
        }
        __syncthreads();

        const uint32_t aBase = uAs + (uint32_t)buf * BUF_STRIDE;
        const uint32_t bBase = uBs + (uint32_t)buf * BUF_STRIDE;

        #pragma unroll
        for (int k8 = 0; k8 < BK / 8; k8++) {
            const uint32_t kByte = (uint32_t)k8 * 32u;   // 8 floats
            uint32_t af[4][4], bf[4][2];
            #pragma unroll
            for (int mt = 0; mt < 4; mt++)
                LDSM4(af[mt][0], af[mt][1], af[mt][2], af[mt][3],
                      aBase + aOff[mt] + kByte);
            LDSM4(bf[0][0], bf[0][1], bf[1][0], bf[1][1], bBase + bOff[0] + kByte);
            LDSM4(bf[2][0], bf[2][1], bf[3][0], bf[3][1], bBase + bOff[1] + kByte);

            #pragma unroll
            for (int mt = 0; mt < 4; mt++)
                #pragma unroll
                for (int nt = 0; nt < 4; nt++)
                    mma8(acc[mt][nt], af[mt], bf[nt]);
        }
        __syncthreads();
    }

    // ---- epilogue ----------------------------------------------------------
    #pragma unroll
    for (int mt = 0; mt < 4; mt++) {
        const int r0 = m0 + wm + mt * 16 + g;
        const int r1 = r0 + 8;
        float bm0 = 0.f, bm1 = 0.f;
        if (MODE == 1 || MODE == 2) { bm0 = bias[r0]; bm1 = bias[r1]; }
        #pragma unroll
        for (int nt = 0; nt < 4; nt++) {
            const int cc = n0 + wn + nt * 8 + tg * 2;
            float v00 = acc[mt][nt][0], v01 = acc[mt][nt][1];
            float v10 = acc[mt][nt][2], v11 = acc[mt][nt][3];
            if (MODE == 0) {
                float b0 = bias[cc], b1 = bias[cc + 1];
                v00 += b0; v01 += b1; v10 += b0; v11 += b1;
            }
            if (MODE == 1 || MODE == 2) {
                v00 += bm0; v01 += bm0; v10 += bm1; v11 += bm1;
            }
            if (MODE == 3) {
                v00 *= ATT_SCALE; v01 *= ATT_SCALE; v10 *= ATT_SCALE; v11 *= ATT_SCALE;
            }
            if (MODE == 2) {
                float2 x0 = *(const float2*)(R + (size_t)r0 * ldd + cc);
                float2 x1 = *(const float2*)(R + (size_t)r1 * ldd + cc);
                v00 += x0.x; v01 += x0.y; v10 += x1.x; v11 += x1.y;
            }
            *(float2*)(D + (size_t)r0 * ldd + cc) = make_float2(v00, v01);
            *(float2*)(D + (size_t)r1 * ldd + cc) = make_float2(v10, v11);
        }
    }
}

// ---------------------------------------------------------------------------
// Transpose: x[b,c,t] -> xT[b,t,c]
// ---------------------------------------------------------------------------
__global__ __launch_bounds__(256) void k_transpose(const float* __restrict__ x,
                                                   float* __restrict__ xT)
{
    __shared__ float tile[32][33];
    const int b  = blockIdx.z;
    const int t0 = blockIdx.x * 32;
    const int c0 = blockIdx.y * 32;
    const int tx = threadIdx.x, ty = threadIdx.y;

    #pragma unroll
    for (int i = ty; i < 32; i += 8)
        tile[i][tx] = x[((size_t)b * CD + c0 + i) * TD + t0 + tx];
    __syncthreads();
    #pragma unroll
    for (int i = ty; i < 32; i += 8)
        xT[((size_t)b * TD + t0 + i) * CD + c0 + tx] = tile[tx][i];
}

// ---------------------------------------------------------------------------
// Row softmax over s in [0, t]; zero-fill (t, next multiple of 128)
// ---------------------------------------------------------------------------
__global__ __launch_bounds__(256) void k_softmax()
{
    const int b = blockIdx.x / TD;
    const int t = blockIdx.x % TD;
    float* p = g_s + (size_t)b * TD * TD + (size_t)t * TD;
    const int n    = t + 1;
    const int ncap = ((t >> 7) + 1) << 7;

    const int tid  = threadIdx.x;
    const int lane = tid & 31;
    const int warp = tid >> 5;

    float vals[16];
    int cnt = 0;
    float mx = -1e30f;
    for (int i = tid; i < n; i += 256) {
        float v = p[i];
        vals[cnt++] = v;
        mx = fmaxf(mx, v);
    }

    __shared__ float red[8];
    #pragma unroll
    for (int o = 16; o; o >>= 1) mx = fmaxf(mx, __shfl_xor_sync(0xffffffffu, mx, o));
    if (lane == 0) red[warp] = mx;
    __syncthreads();
    float m = -1e30f;
    #pragma unroll
    for (int w = 0; w < 8; w++) m = fmaxf(m, red[w]);
    __syncthreads();

    float sum = 0.f;
    for (int i = 0; i < cnt; i++) {
        vals[i] = __expf(vals[i] - m);
        sum += vals[i];
    }
    #pragma unroll
    for (int o = 16; o; o >>= 1) sum += __shfl_xor_sync(0xffffffffu, sum, o);
    if (lane == 0) red[warp] = sum;
    __syncthreads();
    float tot = 0.f;
    #pragma unroll
    for (int w = 0; w < 8; w++) tot += red[w];
    const float inv = 1.0f / tot;

    cnt = 0;
    for (int i = tid; i < n; i += 256) p[i] = vals[cnt++] * inv;
    for (int i = n + tid; i < ncap; i += 256) p[i] = 0.f;
}

// ---------------------------------------------------------------------------
extern "C" void kernel_launch(void* const* d_in, const int* in_sizes, int n_in,
                              void* d_out, int out_size)
{
    const float* x  = (const float*)d_in[0];
    const float* Wq = (const float*)d_in[1];
    const float* bq = (const float*)d_in[2];
    const float* Wk = (const float*)d_in[3];
    const float* bk = (const float*)d_in[4];
    const float* Wv = (const float*)d_in[5];
    const float* bv = (const float*)d_in[6];
    const float* Wp = (const float*)d_in[7];
    const float* bp = (const float*)d_in[8];
    float* out = (float*)d_out;

    float *xT, *q, *k, *vT, *h, *s;
    cudaGetSymbolAddress((void**)&xT, g_xT);
    cudaGetSymbolAddress((void**)&q,  g_q);
    cudaGetSymbolAddress((void**)&k,  g_k);
    cudaGetSymbolAddress((void**)&vT, g_vT);
    cudaGetSymbolAddress((void**)&h,  g_h);
    cudaGetSymbolAddress((void**)&s,  g_s);

    const long TC = (long)TD * CD;
    const long SS = (long)TD * TD;

    cudaFuncSetAttribute(gemm_mma<0>, cudaFuncAttributeMaxDynamicSharedMemorySize, SMEM_BYTES);
    cudaFuncSetAttribute(gemm_mma<1>, cudaFuncAttributeMaxDynamicSharedMemorySize, SMEM_BYTES);
    cudaFuncSetAttribute(gemm_mma<2>, cudaFuncAttributeMaxDynamicSharedMemorySize, SMEM_BYTES);
    cudaFuncSetAttribute(gemm_mma<3>, cudaFuncAttributeMaxDynamicSharedMemorySize, SMEM_BYTES);
    cudaFuncSetAttribute(gemm_mma<4>, cudaFuncAttributeMaxDynamicSharedMemorySize, SMEM_BYTES);

    // 1) transpose x -> xT [B][T][C]
    k_transpose<<<dim3(TD / 32, CD / 32, BB), dim3(32, 8)>>>(x, xT);

    // 2) q = xT . Wq^T + bq ; k likewise       D[t][o], bias by col
    gemm_mma<0><<<dim3(CD / BN, TD / BM, BB), 256, SMEM_BYTES>>>(
        xT, Wq, q, bq, nullptr, CD, CD, CD, TC, 0, TC, CD);
    gemm_mma<0><<<dim3(CD / BN, TD / BM, BB), 256, SMEM_BYTES>>>(
        xT, Wk, k, bk, nullptr, CD, CD, CD, TC, 0, TC, CD);

    // 3) vT = Wv . xT^T + bv  -> [C][T], bias by row
    gemm_mma<1><<<dim3(TD / BN, CD / BM, BB), 256, SMEM_BYTES>>>(
        Wv, xT, vT, bv, nullptr, CD, CD, TD, 0, TC, TC, CD);

    // 4) scores: S[t][s] = scale * q.k^T (causal tiles only)
    gemm_mma<3><<<dim3(TD / BN, TD / BM, BB), 256, SMEM_BYTES>>>(
        q, k, s, nullptr, nullptr, CD, CD, TD, TC, TC, SS, CD);

    // 5) softmax rows (zero-pads to 128-grain for PV)
    k_softmax<<<BB * TD, 256>>>();

    // 6) h = P . vT^T   D[t][c], K variable = (mb+1)*128
    gemm_mma<4><<<dim3(CD / BN, TD / BM, BB), 256, SMEM_BYTES>>>(
        s, vT, h, nullptr, nullptr, TD, TD, CD, SS, TC, TC, 0);

    // 7) out = Wp . h^T + bp + x   D[o][t], bias by row, residual
    gemm_mma<2><<<dim3(TD / BN, CD / BM, BB), 256, SMEM_BYTES>>>(
        Wp, h, out, bp, x, CD, CD, TD, 0, TC, TC, CD);
}

// round 6
// speedup vs baseline: 4.7540x; 1.0051x over previous
#include <cuda_runtime.h>
#include <cstdint>

#define BB 4
#define CD 512
#define TD 4096

// ---------------------------------------------------------------------------
// Device scratch
// ---------------------------------------------------------------------------
__device__ float g_xT[(size_t)BB * TD * CD];   // x transposed: [B][T][C]
__device__ float g_q [(size_t)BB * TD * CD];   // [B][T][C]
__device__ float g_k [(size_t)BB * TD * CD];   // [B][T][C]
__device__ float g_vT[(size_t)BB * TD * CD];   // [B][C][T]
__device__ float g_h [(size_t)BB * TD * CD];   // [B][T][C]
__device__ float g_s [(size_t)BB * TD * TD];   // [B][T][T] scores / probs

// ---------------------------------------------------------------------------
// Helpers (base sm_103 target: mma.sync + cp.async + ldmatrix, no tcgen05)
// ---------------------------------------------------------------------------
__device__ __forceinline__ uint32_t smem_u32(const void* p) {
    uint32_t a;
    asm("{ .reg .u64 t; cvta.to.shared.u64 t, %1; cvt.u32.u64 %0, t; }"
        : "=r"(a) : "l"(p));
    return a;
}

__device__ __forceinline__ void cpa16(uint32_t dst, const float* src) {
    asm volatile("cp.async.cg.shared.global [%0], [%1], 16;"
                 :: "r"(dst), "l"(src));
}
#define CP_COMMIT() asm volatile("cp.async.commit_group;" ::: "memory")
#define CP_WAIT(N)  asm volatile("cp.async.wait_group %0;" :: "n"(N) : "memory")

// ldmatrix x4: four 8x8 b16 tiles (== four 8x4 tf32 tiles)
#define LDSM4(r0, r1, r2, r3, addr) \
    asm volatile("ldmatrix.sync.aligned.m8n8.x4.shared.b16 {%0,%1,%2,%3}, [%4];" \
                 : "=r"(r0), "=r"(r1), "=r"(r2), "=r"(r3) : "r"(addr))

// D += A(16x8) * B(8x8), tf32 in, fp32 accum
__device__ __forceinline__ void mma8(float* c, const uint32_t* a, const uint32_t* b) {
    asm volatile(
        "mma.sync.aligned.m16n8k8.row.col.f32.tf32.tf32.f32 "
        "{%0,%1,%2,%3}, {%4,%5,%6,%7}, {%8,%9}, {%0,%1,%2,%3};"
        : "+f"(c[0]), "+f"(c[1]), "+f"(c[2]), "+f"(c[3])
        : "r"(a[0]), "r"(a[1]), "r"(a[2]), "r"(a[3]),
          "r"(b[0]), "r"(b[1]));
}

// ---------------------------------------------------------------------------
// Tile config
// ---------------------------------------------------------------------------
#define BM 128
#define BN 128
#define BK 32
#define PAD 36           // row pitch in floats; 9x16B granules -> LDSM conflict-free
#define NSTAGE 3
#define ATT_SCALE 0.044194173824159216f  // 1/sqrt(512)

#define SMEM_FLOATS (2 * NSTAGE * BM * PAD)   // 3 bufs x (A + B)
#define SMEM_BYTES  (SMEM_FLOATS * 4)         // 110592 (x2 CTAs = 221184 <= 228KB)
#define BUF_STRIDE  (BM * PAD * 4)            // bytes per buffer per operand

// MODE: 0 = D=A.B^T + bias[n]          (q,k projection)
//       1 = D=A.B^T + bias[m]          (v projection, transposed output)
//       2 = D=A.B^T + bias[m] + resid  (out projection)
//       3 = D=A.B^T * scale, causal tile skip (scores)
//       4 = D=A.B^T, K = (mb+1)*128    (PV)
template <int MODE>
__global__ __launch_bounds__(256, 2) void gemm_mma(
    const float* __restrict__ A, const float* __restrict__ B, float* __restrict__ D,
    const float* __restrict__ bias, const float* __restrict__ resid,
    long lda, long ldb, long ldd, long sA, long sB, long sD, int Kparam)
{
    const int nb = blockIdx.x, bz = blockIdx.z;
    const int mb = (MODE == 3 || MODE == 4) ? (gridDim.y - 1 - blockIdx.y)
                                            : blockIdx.y;
    if (MODE == 3 && nb > mb) return;   // causal tile skip

    const int n0 = nb * BN, m0 = mb * BM;
    const int K = (MODE == 4) ? (mb + 1) * BM : Kparam;
    const int nst = K / BK;             // >= 4 for all modes here

    A += (size_t)bz * sA;
    B += (size_t)bz * sB;
    D += (size_t)bz * sD;
    const float* R = (MODE == 2) ? (resid + (size_t)bz * sD) : nullptr;

    extern __shared__ float sm[];
    float (*As)[BM][PAD] = (float(*)[BM][PAD])sm;                       // [NSTAGE]
    float (*Bs)[BM][PAD] = (float(*)[BM][PAD])(sm + NSTAGE * BM * PAD); // [NSTAGE]

    const int tid  = threadIdx.x;
    const int wid  = tid >> 5;
    const int lane = tid & 31;
    const int g    = lane >> 2;
    const int tg   = lane & 3;
    const int wm   = (wid >> 2) * 64;  // warp m offset in tile
    const int wn   = (wid & 3) * 32;   // warp n offset in tile

    const int ldr = tid >> 3;          // load row
    const int ldq = tid & 7;           // float4 index in row

    // ---- ldmatrix per-lane byte offsets (within one operand buffer) -------
    const int lr = lane & 7;
    const int lt = lane >> 3;
    const uint32_t uAs = smem_u32(sm);
    const uint32_t uBs = uAs + (uint32_t)NSTAGE * BUF_STRIDE;

    uint32_t aOff[4], bOff[2];
    #pragma unroll
    for (int mt = 0; mt < 4; mt++) {
        int row = wm + mt * 16 + (lt & 1) * 8 + lr;
        int col = (lt >> 1) * 4;
        aOff[mt] = (uint32_t)(row * PAD + col) * 4u;
    }
    #pragma unroll
    for (int p = 0; p < 2; p++) {
        int row = wn + p * 16 + (lt >> 1) * 8 + lr;
        int col = (lt & 1) * 4;
        bOff[p] = (uint32_t)(row * PAD + col) * 4u;
    }

    float acc[4][4][4] = {};

    // ---- prologue: prefetch stages 0 and 1 --------------------------------
    #pragma unroll
    for (int p = 0; p < 2; p++) {
        const int k0 = p * BK;
        #pragma unroll
        for (int i = 0; i < 4; i++) {
            int r = ldr + i * 32;
            cpa16(smem_u32(&As[p][r][ldq * 4]), A + (size_t)(m0 + r) * lda + k0 + ldq * 4);
            cpa16(smem_u32(&Bs[p][r][ldq * 4]), B + (size_t)(n0 + r) * ldb + k0 + ldq * 4);
        }
        CP_COMMIT();
    }

    int buf = 0, nbuf = 2;   // compute buffer, prefetch target buffer
    for (int st = 0; st < nst; st++) {
        if (st < nst - 1) { CP_WAIT(1); } else { CP_WAIT(0); }
        __syncthreads();

        // prefetch stage st+2 into nbuf (overlaps with compute below)
        if (st + 2 < nst) {
            const int k0 = (st + 2) * BK;
            #pragma unroll
            for (int i = 0; i < 4; i++) {
                int r = ldr + i * 32;
                cpa16(smem_u32(&As[nbuf][r][ldq * 4]), A + (size_t)(m0 + r) * lda + k0 + ldq * 4);
                cpa16(smem_u32(&Bs[nbuf][r][ldq * 4]), B + (size_t)(n0 + r) * ldb + k0 + ldq * 4);
            }
            CP_COMMIT();
        }

        const uint32_t aBase = uAs + (uint32_t)buf * BUF_STRIDE;
        const uint32_t bBase = uBs + (uint32_t)buf * BUF_STRIDE;

        #pragma unroll
        for (int k8 = 0; k8 < BK / 8; k8++) {
            const uint32_t kByte = (uint32_t)k8 * 32u;
            uint32_t af[4][4], bf[4][2];
            #pragma unroll
            for (int mt = 0; mt < 4; mt++)
                LDSM4(af[mt][0], af[mt][1], af[mt][2], af[mt][3],
                      aBase + aOff[mt] + kByte);
            LDSM4(bf[0][0], bf[0][1], bf[1][0], bf[1][1], bBase + bOff[0] + kByte);
            LDSM4(bf[2][0], bf[2][1], bf[3][0], bf[3][1], bBase + bOff[1] + kByte);

            #pragma unroll
            for (int mt = 0; mt < 4; mt++)
                #pragma unroll
                for (int nt = 0; nt < 4; nt++)
                    mma8(acc[mt][nt], af[mt], bf[nt]);
        }

        buf  = (buf  == NSTAGE - 1) ? 0 : buf + 1;
        nbuf = (nbuf == NSTAGE - 1) ? 0 : nbuf + 1;
    }

    // ---- epilogue ----------------------------------------------------------
    #pragma unroll
    for (int mt = 0; mt < 4; mt++) {
        const int r0 = m0 + wm + mt * 16 + g;
        const int r1 = r0 + 8;
        float bm0 = 0.f, bm1 = 0.f;
        if (MODE == 1 || MODE == 2) { bm0 = bias[r0]; bm1 = bias[r1]; }
        #pragma unroll
        for (int nt = 0; nt < 4; nt++) {
            const int cc = n0 + wn + nt * 8 + tg * 2;
            float v00 = acc[mt][nt][0], v01 = acc[mt][nt][1];
            float v10 = acc[mt][nt][2], v11 = acc[mt][nt][3];
            if (MODE == 0) {
                float b0 = bias[cc], b1 = bias[cc + 1];
                v00 += b0; v01 += b1; v10 += b0; v11 += b1;
            }
            if (MODE == 1 || MODE == 2) {
                v00 += bm0; v01 += bm0; v10 += bm1; v11 += bm1;
            }
            if (MODE == 3) {
                v00 *= ATT_SCALE; v01 *= ATT_SCALE; v10 *= ATT_SCALE; v11 *= ATT_SCALE;
            }
            if (MODE == 2) {
                float2 x0 = *(const float2*)(R + (size_t)r0 * ldd + cc);
                float2 x1 = *(const float2*)(R + (size_t)r1 * ldd + cc);
                v00 += x0.x; v01 += x0.y; v10 += x1.x; v11 += x1.y;
            }
            *(float2*)(D + (size_t)r0 * ldd + cc) = make_float2(v00, v01);
            *(float2*)(D + (size_t)r1 * ldd + cc) = make_float2(v10, v11);
        }
    }
}

// ---------------------------------------------------------------------------
// Transpose: x[b,c,t] -> xT[b,t,c]
// ---------------------------------------------------------------------------
__global__ __launch_bounds__(256) void k_transpose(const float* __restrict__ x,
                                                   float* __restrict__ xT)
{
    __shared__ float tile[32][33];
    const int b  = blockIdx.z;
    const int t0 = blockIdx.x * 32;
    const int c0 = blockIdx.y * 32;
    const int tx = threadIdx.x, ty = threadIdx.y;

    #pragma unroll
    for (int i = ty; i < 32; i += 8)
        tile[i][tx] = x[((size_t)b * CD + c0 + i) * TD + t0 + tx];
    __syncthreads();
    #pragma unroll
    for (int i = ty; i < 32; i += 8)
        xT[((size_t)b * TD + t0 + i) * CD + c0 + tx] = tile[tx][i];
}

// ---------------------------------------------------------------------------
// Row softmax over s in [0, t]; zero-fill (t, next multiple of 128)
// ---------------------------------------------------------------------------
__global__ __launch_bounds__(256) void k_softmax()
{
    const int b = blockIdx.x / TD;
    const int t = blockIdx.x % TD;
    float* p = g_s + (size_t)b * TD * TD + (size_t)t * TD;
    const int n    = t + 1;
    const int ncap = ((t >> 7) + 1) << 7;

    const int tid  = threadIdx.x;
    const int lane = tid & 31;
    const int warp = tid >> 5;

    float vals[16];
    int cnt = 0;
    float mx = -1e30f;
    for (int i = tid; i < n; i += 256) {
        float v = p[i];
        vals[cnt++] = v;
        mx = fmaxf(mx, v);
    }

    __shared__ float red[8];
    #pragma unroll
    for (int o = 16; o; o >>= 1) mx = fmaxf(mx, __shfl_xor_sync(0xffffffffu, mx, o));
    if (lane == 0) red[warp] = mx;
    __syncthreads();
    float m = -1e30f;
    #pragma unroll
    for (int w = 0; w < 8; w++) m = fmaxf(m, red[w]);
    __syncthreads();

    float sum = 0.f;
    for (int i = 0; i < cnt; i++) {
        vals[i] = __expf(vals[i] - m);
        sum += vals[i];
    }
    #pragma unroll
    for (int o = 16; o; o >>= 1) sum += __shfl_xor_sync(0xffffffffu, sum, o);
    if (lane == 0) red[warp] = sum;
    __syncthreads();
    float tot = 0.f;
    #pragma unroll
    for (int w = 0; w < 8; w++) tot += red[w];
    const float inv = 1.0f / tot;

    cnt = 0;
    for (int i = tid; i < n; i += 256) p[i] = vals[cnt++] * inv;
    for (int i = n + tid; i < ncap; i += 256) p[i] = 0.f;
}

// ---------------------------------------------------------------------------
extern "C" void kernel_launch(void* const* d_in, const int* in_sizes, int n_in,
                              void* d_out, int out_size)
{
    const float* x  = (const float*)d_in[0];
    const float* Wq = (const float*)d_in[1];
    const float* bq = (const float*)d_in[2];
    const float* Wk = (const float*)d_in[3];
    const float* bk = (const float*)d_in[4];
    const float* Wv = (const float*)d_in[5];
    const float* bv = (const float*)d_in[6];
    const float* Wp = (const float*)d_in[7];
    const float* bp = (const float*)d_in[8];
    float* out = (float*)d_out;

    float *xT, *q, *k, *vT, *h, *s;
    cudaGetSymbolAddress((void**)&xT, g_xT);
    cudaGetSymbolAddress((void**)&q,  g_q);
    cudaGetSymbolAddress((void**)&k,  g_k);
    cudaGetSymbolAddress((void**)&vT, g_vT);
    cudaGetSymbolAddress((void**)&h,  g_h);
    cudaGetSymbolAddress((void**)&s,  g_s);

    const long TC = (long)TD * CD;
    const long SS = (long)TD * TD;

    cudaFuncSetAttribute(gemm_mma<0>, cudaFuncAttributeMaxDynamicSharedMemorySize, SMEM_BYTES);
    cudaFuncSetAttribute(gemm_mma<1>, cudaFuncAttributeMaxDynamicSharedMemorySize, SMEM_BYTES);
    cudaFuncSetAttribute(gemm_mma<2>, cudaFuncAttributeMaxDynamicSharedMemorySize, SMEM_BYTES);
    cudaFuncSetAttribute(gemm_mma<3>, cudaFuncAttributeMaxDynamicSharedMemorySize, SMEM_BYTES);
    cudaFuncSetAttribute(gemm_mma<4>, cudaFuncAttributeMaxDynamicSharedMemorySize, SMEM_BYTES);

    // 1) transpose x -> xT [B][T][C]
    k_transpose<<<dim3(TD / 32, CD / 32, BB), dim3(32, 8)>>>(x, xT);

    // 2) q = xT . Wq^T + bq ; k likewise       D[t][o], bias by col
    gemm_mma<0><<<dim3(CD / BN, TD / BM, BB), 256, SMEM_BYTES>>>(
        xT, Wq, q, bq, nullptr, CD, CD, CD, TC, 0, TC, CD);
    gemm_mma<0><<<dim3(CD / BN, TD / BM, BB), 256, SMEM_BYTES>>>(
        xT, Wk, k, bk, nullptr, CD, CD, CD, TC, 0, TC, CD);

    // 3) vT = Wv . xT^T + bv  -> [C][T], bias by row
    gemm_mma<1><<<dim3(TD / BN, CD / BM, BB), 256, SMEM_BYTES>>>(
        Wv, xT, vT, bv, nullptr, CD, CD, TD, 0, TC, TC, CD);

    // 4) scores: S[t][s] = scale * q.k^T (causal tiles only)
    gemm_mma<3><<<dim3(TD / BN, TD / BM, BB), 256, SMEM_BYTES>>>(
        q, k, s, nullptr, nullptr, CD, CD, TD, TC, TC, SS, CD);

    // 5) softmax rows (zero-pads to 128-grain for PV)
    k_softmax<<<BB * TD, 256>>>();

    // 6) h = P . vT^T   D[t][c], K variable = (mb+1)*128
    gemm_mma<4><<<dim3(CD / BN, TD / BM, BB), 256, SMEM_BYTES>>>(
        s, vT, h, nullptr, nullptr, TD, TD, CD, SS, TC, TC, 0);

    // 7) out = Wp . h^T + bp + x   D[o][t], bias by row, residual
    gemm_mma<2><<<dim3(TD / BN, CD / BM, BB), 256, SMEM_BYTES>>>(
        Wp, h, out, bp, x, CD, CD, TD, 0, TC, TC, CD);
}

// round 7
// speedup vs baseline: 4.9693x; 1.0453x over previous
#include <cuda_runtime.h>
#include <cstdint>

#define BB 4
#define CD 512
#define TD 4096

// ---------------------------------------------------------------------------
// Device scratch
// ---------------------------------------------------------------------------
__device__ float g_xT[(size_t)BB * TD * CD];   // x transposed: [B][T][C]
__device__ float g_q [(size_t)BB * TD * CD];   // [B][T][C]
__device__ float g_k [(size_t)BB * TD * CD];   // [B][T][C]
__device__ float g_vT[(size_t)BB * TD * CD];   // [B][C][T]
__device__ float g_h [(size_t)BB * TD * CD];   // [B][T][C]
__device__ float g_s [(size_t)BB * TD * TD];   // [B][T][T] unnormalized probs
__device__ float g_rs[(size_t)BB * TD];        // row sums of exp

// ---------------------------------------------------------------------------
// Helpers (base sm_103 target: mma.sync + cp.async + ldmatrix, no tcgen05)
// ---------------------------------------------------------------------------
__device__ __forceinline__ uint32_t smem_u32(const void* p) {
    uint32_t a;
    asm("{ .reg .u64 t; cvta.to.shared.u64 t, %1; cvt.u32.u64 %0, t; }"
        : "=r"(a) : "l"(p));
    return a;
}

__device__ __forceinline__ void cpa16(uint32_t dst, const float* src) {
    asm volatile("cp.async.cg.shared.global [%0], [%1], 16;"
                 :: "r"(dst), "l"(src));
}
#define CP_COMMIT() asm volatile("cp.async.commit_group;" ::: "memory")
#define CP_WAIT(N)  asm volatile("cp.async.wait_group %0;" :: "n"(N) : "memory")

// ldmatrix x4: four 8x8 b16 tiles (== four 8x4 tf32 tiles)
#define LDSM4(r0, r1, r2, r3, addr) \
    asm volatile("ldmatrix.sync.aligned.m8n8.x4.shared.b16 {%0,%1,%2,%3}, [%4];" \
                 : "=r"(r0), "=r"(r1), "=r"(r2), "=r"(r3) : "r"(addr))

// D += A(16x8) * B(8x8), tf32 in, fp32 accum
__device__ __forceinline__ void mma8(float* c, const uint32_t* a, const uint32_t* b) {
    asm volatile(
        "mma.sync.aligned.m16n8k8.row.col.f32.tf32.tf32.f32 "
        "{%0,%1,%2,%3}, {%4,%5,%6,%7}, {%8,%9}, {%0,%1,%2,%3};"
        : "+f"(c[0]), "+f"(c[1]), "+f"(c[2]), "+f"(c[3])
        : "r"(a[0]), "r"(a[1]), "r"(a[2]), "r"(a[3]),
          "r"(b[0]), "r"(b[1]));
}

// ---------------------------------------------------------------------------
// Tile config
// ---------------------------------------------------------------------------
#define BM 128
#define BN 128
#define BK 32
#define PAD 36           // row pitch in floats; 9x16B granules -> LDSM conflict-free
#define NSTAGE 3
#define ATT_SCALE 0.044194173824159216f  // 1/sqrt(512)

#define SMEM_FLOATS (2 * NSTAGE * BM * PAD)   // 3 bufs x (A + B)
#define SMEM_BYTES  (SMEM_FLOATS * 4)         // 110592 (x2 CTAs <= 228KB)
#define BUF_STRIDE  (BM * PAD * 4)            // bytes per buffer per operand

// MODE: 0 = D=A.B^T + bias[n]                       (q,k projection)
//       1 = D=A.B^T + bias[m]                       (v projection, transposed out)
//       2 = D=A.B^T + bias[m] + resid               (out projection)
//       3 = D=exp(A.B^T*scale) causal-masked        (scores -> unnorm probs)
//       4 = D=(A.B^T)/rowsum[m], K=(mb+1)*128       (PV, normalize)
template <int MODE>
__global__ __launch_bounds__(256, 2) void gemm_mma(
    const float* __restrict__ A, const float* __restrict__ B, float* __restrict__ D,
    const float* __restrict__ bias, const float* __restrict__ resid,
    long lda, long ldb, long ldd, long sA, long sB, long sD, int Kparam)
{
    const int nb = blockIdx.x, bz = blockIdx.z;
    const int mb = (MODE == 3 || MODE == 4) ? (gridDim.y - 1 - blockIdx.y)
                                            : blockIdx.y;
    if (MODE == 3 && nb > mb) return;   // causal tile skip

    const int n0 = nb * BN, m0 = mb * BM;
    const int K = (MODE == 4) ? (mb + 1) * BM : Kparam;
    const int nst = K / BK;

    A += (size_t)bz * sA;
    B += (size_t)bz * sB;
    D += (size_t)bz * sD;
    const float* R = (MODE == 2) ? (resid + (size_t)bz * sD) : nullptr;
    const float* RS = (MODE == 4) ? (bias + (size_t)bz * TD) : nullptr;  // rowsums

    extern __shared__ float sm[];
    float (*As)[BM][PAD] = (float(*)[BM][PAD])sm;                       // [NSTAGE]
    float (*Bs)[BM][PAD] = (float(*)[BM][PAD])(sm + NSTAGE * BM * PAD); // [NSTAGE]

    const int tid  = threadIdx.x;
    const int wid  = tid >> 5;
    const int lane = tid & 31;
    const int g    = lane >> 2;
    const int tg   = lane & 3;
    const int wm   = (wid >> 2) * 64;
    const int wn   = (wid & 3) * 32;

    const int ldr = tid >> 3;
    const int ldq = tid & 7;

    const int lr = lane & 7;
    const int lt = lane >> 3;
    const uint32_t uAs = smem_u32(sm);
    const uint32_t uBs = uAs + (uint32_t)NSTAGE * BUF_STRIDE;

    uint32_t aOff[4], bOff[2];
    #pragma unroll
    for (int mt = 0; mt < 4; mt++) {
        int row = wm + mt * 16 + (lt & 1) * 8 + lr;
        int col = (lt >> 1) * 4;
        aOff[mt] = (uint32_t)(row * PAD + col) * 4u;
    }
    #pragma unroll
    for (int p = 0; p < 2; p++) {
        int row = wn + p * 16 + (lt >> 1) * 8 + lr;
        int col = (lt & 1) * 4;
        bOff[p] = (uint32_t)(row * PAD + col) * 4u;
    }

    float acc[4][4][4] = {};

    // ---- prologue: prefetch stages 0 and 1 --------------------------------
    #pragma unroll
    for (int p = 0; p < 2; p++) {
        const int k0 = p * BK;
        #pragma unroll
        for (int i = 0; i < 4; i++) {
            int r = ldr + i * 32;
            cpa16(smem_u32(&As[p][r][ldq * 4]), A + (size_t)(m0 + r) * lda + k0 + ldq * 4);
            cpa16(smem_u32(&Bs[p][r][ldq * 4]), B + (size_t)(n0 + r) * ldb + k0 + ldq * 4);
        }
        CP_COMMIT();
    }

    int buf = 0, nbuf = 2;
    for (int st = 0; st < nst; st++) {
        if (st < nst - 1) { CP_WAIT(1); } else { CP_WAIT(0); }
        __syncthreads();

        if (st + 2 < nst) {
            const int k0 = (st + 2) * BK;
            #pragma unroll
            for (int i = 0; i < 4; i++) {
                int r = ldr + i * 32;
                cpa16(smem_u32(&As[nbuf][r][ldq * 4]), A + (size_t)(m0 + r) * lda + k0 + ldq * 4);
                cpa16(smem_u32(&Bs[nbuf][r][ldq * 4]), B + (size_t)(n0 + r) * ldb + k0 + ldq * 4);
            }
            CP_COMMIT();
        }

        const uint32_t aBase = uAs + (uint32_t)buf * BUF_STRIDE;
        const uint32_t bBase = uBs + (uint32_t)buf * BUF_STRIDE;

        #pragma unroll
        for (int k8 = 0; k8 < BK / 8; k8++) {
            const uint32_t kByte = (uint32_t)k8 * 32u;
            uint32_t af[4][4], bf[4][2];
            #pragma unroll
            for (int mt = 0; mt < 4; mt++)
                LDSM4(af[mt][0], af[mt][1], af[mt][2], af[mt][3],
                      aBase + aOff[mt] + kByte);
            LDSM4(bf[0][0], bf[0][1], bf[1][0], bf[1][1], bBase + bOff[0] + kByte);
            LDSM4(bf[2][0], bf[2][1], bf[3][0], bf[3][1], bBase + bOff[1] + kByte);

            #pragma unroll
            for (int mt = 0; mt < 4; mt++)
                #pragma unroll
                for (int nt = 0; nt < 4; nt++)
                    mma8(acc[mt][nt], af[mt], bf[nt]);
        }

        buf  = (buf  == NSTAGE - 1) ? 0 : buf + 1;
        nbuf = (nbuf == NSTAGE - 1) ? 0 : nbuf + 1;
    }

    // ---- epilogue ----------------------------------------------------------
    const bool diag = (MODE == 3) && (nb == mb);

    #pragma unroll
    for (int mt = 0; mt < 4; mt++) {
        const int r0 = m0 + wm + mt * 16 + g;
        const int r1 = r0 + 8;
        float bm0 = 0.f, bm1 = 0.f;
        if (MODE == 1 || MODE == 2) { bm0 = bias[r0]; bm1 = bias[r1]; }
        float ri0 = 1.f, ri1 = 1.f;
        if (MODE == 4) { ri0 = 1.0f / RS[r0]; ri1 = 1.0f / RS[r1]; }
        #pragma unroll
        for (int nt = 0; nt < 4; nt++) {
            const int cc = n0 + wn + nt * 8 + tg * 2;
            float v00 = acc[mt][nt][0], v01 = acc[mt][nt][1];
            float v10 = acc[mt][nt][2], v11 = acc[mt][nt][3];
            if (MODE == 0) {
                float b0 = bias[cc], b1 = bias[cc + 1];
                v00 += b0; v01 += b1; v10 += b0; v11 += b1;
            }
            if (MODE == 1 || MODE == 2) {
                v00 += bm0; v01 += bm0; v10 += bm1; v11 += bm1;
            }
            if (MODE == 3) {
                // unnormalized softmax weights; causal mask on diagonal tile
                v00 = __expf(v00 * ATT_SCALE);
                v01 = __expf(v01 * ATT_SCALE);
                v10 = __expf(v10 * ATT_SCALE);
                v11 = __expf(v11 * ATT_SCALE);
                if (diag) {
                    if (cc     > r0) v00 = 0.f;
                    if (cc + 1 > r0) v01 = 0.f;
                    if (cc     > r1) v10 = 0.f;
                    if (cc + 1 > r1) v11 = 0.f;
                }
            }
            if (MODE == 4) {
                v00 *= ri0; v01 *= ri0; v10 *= ri1; v11 *= ri1;
            }
            if (MODE == 2) {
                float2 x0 = *(const float2*)(R + (size_t)r0 * ldd + cc);
                float2 x1 = *(const float2*)(R + (size_t)r1 * ldd + cc);
                v00 += x0.x; v01 += x0.y; v10 += x1.x; v11 += x1.y;
            }
            *(float2*)(D + (size_t)r0 * ldd + cc) = make_float2(v00, v01);
            *(float2*)(D + (size_t)r1 * ldd + cc) = make_float2(v10, v11);
        }
    }
}

// ---------------------------------------------------------------------------
// Transpose: x[b,c,t] -> xT[b,t,c]
// ---------------------------------------------------------------------------
__global__ __launch_bounds__(256) void k_transpose(const float* __restrict__ x,
                                                   float* __restrict__ xT)
{
    __shared__ float tile[32][33];
    const int b  = blockIdx.z;
    const int t0 = blockIdx.x * 32;
    const int c0 = blockIdx.y * 32;
    const int tx = threadIdx.x, ty = threadIdx.y;

    #pragma unroll
    for (int i = ty; i < 32; i += 8)
        tile[i][tx] = x[((size_t)b * CD + c0 + i) * TD + t0 + tx];
    __syncthreads();
    #pragma unroll
    for (int i = ty; i < 32; i += 8)
        xT[((size_t)b * TD + t0 + i) * CD + c0 + tx] = tile[tx][i];
}

// ---------------------------------------------------------------------------
// Row sums of unnormalized probs: rs[b][t] = sum_{s<=t} P[b][t][s]
// ---------------------------------------------------------------------------
__global__ __launch_bounds__(256) void k_rowsum()
{
    const int b = blockIdx.x / TD;
    const int t = blockIdx.x % TD;
    const float* p = g_s + (size_t)b * TD * TD + (size_t)t * TD;
    const int n = t + 1;

    const int tid  = threadIdx.x;
    const int lane = tid & 31;
    const int warp = tid >> 5;

    float sum = 0.f;
    const int n4 = n >> 2;           // number of full float4s
    const float4* p4 = (const float4*)p;
    for (int i = tid; i < n4; i += 256) {
        float4 v = p4[i];
        sum += (v.x + v.y) + (v.z + v.w);
    }
    for (int i = n4 * 4 + tid; i < n; i += 256) sum += p[i];

    __shared__ float red[8];
    #pragma unroll
    for (int o = 16; o; o >>= 1) sum += __shfl_xor_sync(0xffffffffu, sum, o);
    if (lane == 0) red[warp] = sum;
    __syncthreads();
    if (tid == 0) {
        float tot = 0.f;
        #pragma unroll
        for (int w = 0; w < 8; w++) tot += red[w];
        g_rs[(size_t)b * TD + t] = tot;
    }
}

// ---------------------------------------------------------------------------
extern "C" void kernel_launch(void* const* d_in, const int* in_sizes, int n_in,
                              void* d_out, int out_size)
{
    const float* x  = (const float*)d_in[0];
    const float* Wq = (const float*)d_in[1];
    const float* bq = (const float*)d_in[2];
    const float* Wk = (const float*)d_in[3];
    const float* bk = (const float*)d_in[4];
    const float* Wv = (const float*)d_in[5];
    const float* bv = (const float*)d_in[6];
    const float* Wp = (const float*)d_in[7];
    const float* bp = (const float*)d_in[8];
    float* out = (float*)d_out;

    float *xT, *q, *k, *vT, *h, *s, *rs;
    cudaGetSymbolAddress((void**)&xT, g_xT);
    cudaGetSymbolAddress((void**)&q,  g_q);
    cudaGetSymbolAddress((void**)&k,  g_k);
    cudaGetSymbolAddress((void**)&vT, g_vT);
    cudaGetSymbolAddress((void**)&h,  g_h);
    cudaGetSymbolAddress((void**)&s,  g_s);
    cudaGetSymbolAddress((void**)&rs, g_rs);

    const long TC = (long)TD * CD;
    const long SS = (long)TD * TD;

    cudaFuncSetAttribute(gemm_mma<0>, cudaFuncAttributeMaxDynamicSharedMemorySize, SMEM_BYTES);
    cudaFuncSetAttribute(gemm_mma<1>, cudaFuncAttributeMaxDynamicSharedMemorySize, SMEM_BYTES);
    cudaFuncSetAttribute(gemm_mma<2>, cudaFuncAttributeMaxDynamicSharedMemorySize, SMEM_BYTES);
    cudaFuncSetAttribute(gemm_mma<3>, cudaFuncAttributeMaxDynamicSharedMemorySize, SMEM_BYTES);
    cudaFuncSetAttribute(gemm_mma<4>, cudaFuncAttributeMaxDynamicSharedMemorySize, SMEM_BYTES);

    // 1) transpose x -> xT [B][T][C]
    k_transpose<<<dim3(TD / 32, CD / 32, BB), dim3(32, 8)>>>(x, xT);

    // 2) q = xT . Wq^T + bq ; k likewise
    gemm_mma<0><<<dim3(CD / BN, TD / BM, BB), 256, SMEM_BYTES>>>(
        xT, Wq, q, bq, nullptr, CD, CD, CD, TC, 0, TC, CD);
    gemm_mma<0><<<dim3(CD / BN, TD / BM, BB), 256, SMEM_BYTES>>>(
        xT, Wk, k, bk, nullptr, CD, CD, CD, TC, 0, TC, CD);

    // 3) vT = Wv . xT^T + bv  -> [C][T]
    gemm_mma<1><<<dim3(TD / BN, CD / BM, BB), 256, SMEM_BYTES>>>(
        Wv, xT, vT, bv, nullptr, CD, CD, TD, 0, TC, TC, CD);

    // 4) unnormalized probs: P = exp(scale * q.k^T), causal-masked
    gemm_mma<3><<<dim3(TD / BN, TD / BM, BB), 256, SMEM_BYTES>>>(
        q, k, s, nullptr, nullptr, CD, CD, TD, TC, TC, SS, CD);

    // 5) row sums
    k_rowsum<<<BB * TD, 256>>>();

    // 6) h = (P . vT^T) / rowsum
    gemm_mma<4><<<dim3(CD / BN, TD / BM, BB), 256, SMEM_BYTES>>>(
        s, vT, h, rs, nullptr, TD, TD, CD, SS, TC, TC, 0);

    // 7) out = Wp . h^T + bp + x
    gemm_mma<2><<<dim3(TD / BN, CD / BM, BB), 256, SMEM_BYTES>>>(
        Wp, h, out, bp, x, CD, CD, TD, 0, TC, TC, CD);
}